// round 14
// baseline (speedup 1.0000x reference)
#include <cuda_runtime.h>
#include <cuda_bf16.h>
#include <cstdint>

#define Bb 64
#define Vv 64
#define Tt 256
#define Ff 64
#define NEG_SLOPE 0.01f

// Transposed X: XT[t][b][w] = X[b][w][t] (makes fused-kernel X loads coalesced)
__device__ float g_XT[(size_t)Tt * Bb * Vv];     // 4 MB

__device__ __forceinline__ float fast_sigmoid(float x) {
    // sigmoid(x) = 0.5 + 0.5*tanh(0.5*x): single MUFU.TANH instead of EX2+RCP.
    float th;
    asm("tanh.approx.f32 %0, %1;" : "=f"(th) : "f"(0.5f * x));
    return fmaf(0.5f, th, 0.5f);
}

// ---------------------------------------------------------------------------
// X transpose (only prep; hidden under fused's sigmoid phase via PDL).
// ---------------------------------------------------------------------------
__global__ __launch_bounds__(256) void x_transpose(const float* __restrict__ X) {
    const int t0 = (blockIdx.x & 7) * 32;        // 0..224
    const int b  = (blockIdx.x >> 3) & 63;       // 0..63
    const int w0 = (blockIdx.x >> 9) * 32;       // 0 or 32

    __shared__ float sm[32][33];

    const int tid = threadIdx.x;
    const int j  = tid & 31;
    const int i0 = tid >> 5;                     // 0..7

#pragma unroll
    for (int k = 0; k < 4; k++) {
        int i = i0 + k * 8;
        sm[i][j] = X[((size_t)b * Vv + (w0 + i)) * Tt + (t0 + j)];
    }
    __syncthreads();
#pragma unroll
    for (int k = 0; k < 4; k++) {
        int i = i0 + k * 8;
        g_XT[(size_t)(t0 + i) * (Bb * Vv) + (size_t)b * Vv + (w0 + j)] = sm[j][i];
    }
}

// ---------------------------------------------------------------------------
// Fused sigmoid + GEMM + expand. Block = (t, v-group of 8): sigmoid with
// ZERO chip-wide redundancy, no adj materialization, no adjT smem staging.
// R11 retry with the actual bug fixed: all smem arrays PADDED off power-of-
// two strides (R11's 58us came from 8-way LDS conflicts at stride 256B/64f).
//   sAdj[8][68]  -> GEMM A-reads bank offsets {0,4,..,28}: conflict-free
//   sXT [64][68] -> GEMM X-reads offsets {0,4,8,12} + 8-lane broadcast: free
//   sH  [8][65]  -> STS collisions broken
// Stores: per b a 2 KB contiguous segment (128 thr x STG.128), 64 segments.
// ---------------------------------------------------------------------------
__global__ __launch_bounds__(256) void fused_kernel(const float* __restrict__ A,
                                                    const float* __restrict__ W,
                                                    float* __restrict__ out) {
    const int t  = blockIdx.x;
    const int v0 = blockIdx.y << 3;    // 0,8,...,56

    __shared__ float sAdj[8 * 68];     // padded rows
    __shared__ float sXT[64 * 68];     // padded rows
    __shared__ float sH[8 * 65];       // padded rows

    const int tid = threadIdx.x;

    // ---- Phase A (pre-PDL-sync): W preselect + adj sigmoid ----
    float4 w4 = reinterpret_cast<const float4*>(W)[tid & 15];
    float4 wp, wn;
    wp.x = (w4.x >= 0.f) ? w4.x : NEG_SLOPE * w4.x;
    wp.y = (w4.y >= 0.f) ? w4.y : NEG_SLOPE * w4.y;
    wp.z = (w4.z >= 0.f) ? w4.z : NEG_SLOPE * w4.z;
    wp.w = (w4.w >= 0.f) ? w4.w : NEG_SLOPE * w4.w;
    wn.x = (w4.x >= 0.f) ? NEG_SLOPE * w4.x : w4.x;
    wn.y = (w4.y >= 0.f) ? NEG_SLOPE * w4.y : w4.y;
    wn.z = (w4.z >= 0.f) ? NEG_SLOPE * w4.z : w4.z;
    wn.w = (w4.w >= 0.f) ? NEG_SLOPE * w4.w : w4.w;

    if (tid < 128) {                   // 8 rows x 16 float4
        int vloc = tid >> 4, wq = tid & 15;
        int v = v0 + vloc;
        float4 a = reinterpret_cast<const float4*>(A)[(size_t)t * 1024 + (size_t)v * 16 + wq];
        float4 r;
        r.x = (v == 4 * wq + 0) ? 1.0f : fast_sigmoid(a.x);
        r.y = (v == 4 * wq + 1) ? 1.0f : fast_sigmoid(a.y);
        r.z = (v == 4 * wq + 2) ? 1.0f : fast_sigmoid(a.z);
        r.w = (v == 4 * wq + 3) ? 1.0f : fast_sigmoid(a.w);
        reinterpret_cast<float4*>(sAdj)[vloc * 17 + wq] = r;
    }

    // ---- Wait for x_transpose grid (PDL) ----
    cudaGridDependencySynchronize();

    // ---- Phase B: load XT[t] (16 KB, fully coalesced) into padded rows ----
    {
        const float4* src = reinterpret_cast<const float4*>(g_XT) + (size_t)t * 1024;
        float4* dst = reinterpret_cast<float4*>(sXT);
#pragma unroll
        for (int k = 0; k < 4; k++) {
            int idx = tid + k * 256;           // b*16 + wq
            int b = idx >> 4, wq = idx & 15;
            dst[b * 17 + wq] = src[idx];
        }
    }
    __syncthreads();

    // ---- Phase C: GEMM. thread (b = tid>>3, vloc = tid&7) -> h[vloc][b], h[vloc][b+32]
    {
        const int b    = tid >> 3;             // 0..31
        const int vloc = tid & 7;
        const float4* arow = reinterpret_cast<const float4*>(sAdj) + vloc * 17;
        const float4* x0q  = reinterpret_cast<const float4*>(sXT) + b * 17;
        const float4* x1q  = reinterpret_cast<const float4*>(sXT) + (b + 32) * 17;
        float a0 = 0.f, a1 = 0.f;
#pragma unroll
        for (int wq = 0; wq < 16; wq++) {
            float4 s  = arow[wq];
            float4 x0 = x0q[wq];
            float4 x1 = x1q[wq];
            a0 = fmaf(s.x, x0.x, fmaf(s.y, x0.y, fmaf(s.z, x0.z, fmaf(s.w, x0.w, a0))));
            a1 = fmaf(s.x, x1.x, fmaf(s.y, x1.y, fmaf(s.z, x1.z, fmaf(s.w, x1.w, a1))));
        }
        sH[vloc * 65 + b] = a0;
        sH[vloc * 65 + b + 32] = a1;
    }
    __syncthreads();

    // ---- Phase D: stores. Per b a 2 KB contiguous segment (8v x 64f). ----
    float4* obase = reinterpret_cast<float4*>(out) + (size_t)t * 1024 + (size_t)v0 * 16;
    const int q  = tid & 127;          // segment float4 idx: v = q>>4, f4 = q&15
    const int bh = tid >> 7;           // 0 or 1
    const float* hrow = sH + (q >> 4) * 65;
#pragma unroll
    for (int it = 0; it < 32; it++) {
        int bb = it * 2 + bh;
        float h = hrow[bb];
        bool pos = (h >= 0.f);
        float4 r;
        r.x = h * (pos ? wp.x : wn.x);
        r.y = h * (pos ? wp.y : wn.y);
        r.z = h * (pos ? wp.z : wn.z);
        r.w = h * (pos ? wp.w : wn.w);
        __stcs(obase + (size_t)bb * (Tt * 1024) + q, r);
    }
}

extern "C" void kernel_launch(void* const* d_in, const int* in_sizes, int n_in,
                              void* d_out, int out_size) {
    const float* X = (const float*)d_in[0];   // [B, V, T]
    const float* A = (const float*)d_in[1];   // [T, V, V]
    const float* W = (const float*)d_in[2];   // [F, 1]
    float* out = (float*)d_out;               // [B, T, V*F]

    x_transpose<<<1024, 256>>>(X);

    cudaLaunchConfig_t cfg = {};
    cfg.gridDim  = dim3(Tt, Vv / 8);
    cfg.blockDim = dim3(256);
    cfg.dynamicSmemBytes = 0;
    cfg.stream = 0;
    cudaLaunchAttribute attr[1];
    attr[0].id = cudaLaunchAttributeProgrammaticStreamSerialization;
    attr[0].val.programmaticStreamSerializationAllowed = 1;
    cfg.attrs = attr;
    cfg.numAttrs = 1;
    cudaLaunchKernelEx(&cfg, fused_kernel, A, W, (float*)d_out);
}

// round 16
// speedup vs baseline: 1.0138x; 1.0138x over previous
#include <cuda_runtime.h>
#include <cuda_bf16.h>
#include <cstdint>

#define Bb 64
#define Vv 64
#define Tt 256
#define Ff 64
#define NEG_SLOPE 0.01f

// Precomputed adjacency, SAME layout as A: adj[t][v][w] = sigmoid(A) off-diag, 1 on diag.
__device__ float g_adj[(size_t)Tt * Vv * Vv];   // 4 MB

__device__ __forceinline__ float fast_sigmoid(float x) {
    float th;
    asm("tanh.approx.f32 %0, %1;" : "=f"(th) : "f"(0.5f * x));
    return fmaf(0.5f, th, 0.5f);
}

// ---------------------------------------------------------------------------
// Prep: PURE elementwise (no transpose, no smem, no sync): 1 float4/thread,
// coalesced in/out, tanh-based. Cheapest possible prep (~1.3us).
// ---------------------------------------------------------------------------
__global__ __launch_bounds__(256) void adj_sig(const float* __restrict__ A) {
    const int idx4 = blockIdx.x * 256 + threadIdx.x;   // 0..262143
    const int v  = (idx4 >> 4) & 63;
    const int wq = idx4 & 15;
    float4 a = reinterpret_cast<const float4*>(A)[idx4];
    float4 r;
    r.x = (v == 4 * wq + 0) ? 1.0f : fast_sigmoid(a.x);
    r.y = (v == 4 * wq + 1) ? 1.0f : fast_sigmoid(a.y);
    r.z = (v == 4 * wq + 2) ? 1.0f : fast_sigmoid(a.z);
    r.w = (v == 4 * wq + 3) ? 1.0f : fast_sigmoid(a.w);
    reinterpret_cast<float4*>(g_adj)[idx4] = r;
}

// ---------------------------------------------------------------------------
// Fused GEMM + expand, WARP-PIPELINED. R4 grid (2048 blocks, 256 thr,
// ~21 KB smem) but warp bb owns b-row b0+bb end-to-end: GEMM(all 64 v) ->
// syncwarp -> store 16 KB tile. Only ONE block-wide sync (post staging), so
// warps desynchronize (hi-wid-first arbiter) and wave-1 GEMM overlaps
// wave-1 stores instead of serializing chip-wide in front of them.
// sAdj float4-XOR swizzle: (v,wq) at [v*16 + (wq ^ (v&15))] -> per-lane row
// reads hit every bank-quad uniformly (min-wavefront LDS.128).
// ---------------------------------------------------------------------------
__global__ __launch_bounds__(256) void fused_kernel(const float* __restrict__ X,
                                                    const float* __restrict__ W,
                                                    float* __restrict__ out) {
    const int t  = blockIdx.x;
    const int b0 = blockIdx.y << 3;    // 0,8,...,56

    __shared__ float4 sAdj4[Vv * 16];  // 16 KB, swizzled [v][wq]
    __shared__ float  sX[8][68];       // padded rows
    __shared__ float  sH[8][68];       // padded rows

    const int tid  = threadIdx.x;
    const int lane = tid & 31;
    const int bb   = tid >> 5;         // warp id == owned b-row

    // W preselect for this thread's f-group: leaky(h*w) = h * (h>=0 ? wp : wn)
    float4 w4 = reinterpret_cast<const float4*>(W)[lane & 15];
    float4 wp, wn;
    wp.x = (w4.x >= 0.f) ? w4.x : NEG_SLOPE * w4.x;
    wp.y = (w4.y >= 0.f) ? w4.y : NEG_SLOPE * w4.y;
    wp.z = (w4.z >= 0.f) ? w4.z : NEG_SLOPE * w4.z;
    wp.w = (w4.w >= 0.f) ? w4.w : NEG_SLOPE * w4.w;
    wn.x = (w4.x >= 0.f) ? NEG_SLOPE * w4.x : w4.x;
    wn.y = (w4.y >= 0.f) ? NEG_SLOPE * w4.y : w4.y;
    wn.z = (w4.z >= 0.f) ? NEG_SLOPE * w4.z : w4.z;
    wn.w = (w4.w >= 0.f) ? NEG_SLOPE * w4.w : w4.w;

    // ---- Stage adj[t] with float4 XOR swizzle (coalesced LDG.128) ----
    {
        const float4* src = reinterpret_cast<const float4*>(g_adj) + (size_t)t * 1024;
#pragma unroll
        for (int k = 0; k < 4; k++) {
            int idx = tid + k * 256;          // v*16 + wq
            int v = idx >> 4, wq = idx & 15;
            sAdj4[v * 16 + (wq ^ (v & 15))] = src[idx];
        }
    }
    // ---- Gather X[b0..b0+7][*][t] ----
#pragma unroll
    for (int k = 0; k < 2; k++) {
        int idx = tid + k * 256;              // bb*64 + w
        int bbg = idx >> 6, w = idx & 63;
        sX[bbg][w] = __ldg(&X[((size_t)(b0 + bbg) * Vv + w) * Tt + t]);
    }
    __syncthreads();   // the ONLY block-wide sync

    // ---- Per-warp GEMM: lane v computes h[v], h[v+32] for row bb ----
    {
        const int v = lane;
        const int sw = v & 15;
        const float4* xr = reinterpret_cast<const float4*>(&sX[bb][0]);   // 17-f4 row
        float a0 = 0.f, a1 = 0.f;
#pragma unroll 4
        for (int j = 0; j < 16; j++) {
            float4 xx = xr[j];                        // warp broadcast
            float4 s0 = sAdj4[v * 16 + (j ^ sw)];
            float4 s1 = sAdj4[(v + 32) * 16 + (j ^ sw)];
            a0 = fmaf(s0.x, xx.x, fmaf(s0.y, xx.y, fmaf(s0.z, xx.z, fmaf(s0.w, xx.w, a0))));
            a1 = fmaf(s1.x, xx.x, fmaf(s1.y, xx.y, fmaf(s1.z, xx.z, fmaf(s1.w, xx.w, a1))));
        }
        sH[bb][v] = a0;
        sH[bb][v + 32] = a1;
    }
    __syncwarp();

    // ---- Per-warp store: 16 KB tile, 512B/warp-instr coalesced ----
    {
        float4* o = reinterpret_cast<float4*>(out) + ((size_t)(b0 + bb) * Tt + t) * 1024;
        const int f4 = lane & 15;
        const int vh = lane >> 4;
        const float* hrow = &sH[bb][0];
#pragma unroll
        for (int k = 0; k < 32; k++) {
            int v = 2 * k + vh;
            float h = hrow[v];
            bool pos = (h >= 0.f);
            float4 r;
            r.x = h * (pos ? wp.x : wn.x);
            r.y = h * (pos ? wp.y : wn.y);
            r.z = h * (pos ? wp.z : wn.z);
            r.w = h * (pos ? wp.w : wn.w);
            __stcs(o + v * 16 + f4, r);
        }
    }
}

extern "C" void kernel_launch(void* const* d_in, const int* in_sizes, int n_in,
                              void* d_out, int out_size) {
    const float* X = (const float*)d_in[0];   // [B, V, T]
    const float* A = (const float*)d_in[1];   // [T, V, V]
    const float* W = (const float*)d_in[2];   // [F, 1]
    float* out = (float*)d_out;               // [B, T, V*F]

    adj_sig<<<1024, 256>>>(A);
    dim3 grid(Tt, Bb / 8);
    fused_kernel<<<grid, 256>>>(X, W, out);
}